// round 1
// baseline (speedup 1.0000x reference)
#include <cuda_runtime.h>
#include <math.h>

// Problem dims
#define B_  2
#define S_  2048
#define D_  1024
#define H_  16
#define DH_ 64
#define M_  4096
#define R_  (B_*S_)   // 4096 rows total

// ---------------- scratch (__device__ globals: allocation-free) ----------------
__device__ float g_h    [(size_t)R_*D_];
__device__ float g_q    [(size_t)R_*D_];
__device__ float g_k    [(size_t)R_*D_];
__device__ float g_v    [(size_t)R_*D_];
__device__ float g_ctx  [(size_t)R_*D_];
__device__ float g_mlpin[(size_t)R_*D_];
__device__ float g_h2   [(size_t)R_*D_];
__device__ float g_ff1  [(size_t)R_*M_];
__device__ float g_sc   [(size_t)B_*H_*S_*S_];   // 512 MB scores scratch

// ---------------- helpers ----------------
__device__ __forceinline__ float gelu_f(float x){
    const float c = 0.7978845608028654f;  // sqrt(2/pi)
    return 0.5f * x * (1.0f + tanhf(c * (x + 0.044715f * x * x * x)));
}

// ---------------- LayerNorm (one block per row, D=1024, 256 threads) ----------------
__global__ __launch_bounds__(256) void layernorm_k(
    const float* __restrict__ x, const float* __restrict__ s,
    const float* __restrict__ b, float* __restrict__ y)
{
    size_t row = blockIdx.x;
    int t = threadIdx.x;
    const float4* xr = (const float4*)(x + row * (size_t)D_);
    float4 v = xr[t];
    float sum = v.x + v.y + v.z + v.w;
    float sq  = v.x*v.x + v.y*v.y + v.z*v.z + v.w*v.w;

    __shared__ float sh[64];
    int lane = t & 31, w = t >> 5;
    #pragma unroll
    for (int o = 16; o; o >>= 1) {
        sum += __shfl_xor_sync(~0u, sum, o);
        sq  += __shfl_xor_sync(~0u, sq,  o);
    }
    if (!lane) { sh[w] = sum; sh[w + 32] = sq; }
    __syncthreads();
    if (t < 32) {
        float s2 = (t < 8) ? sh[t]      : 0.0f;
        float q2 = (t < 8) ? sh[t + 32] : 0.0f;
        #pragma unroll
        for (int o = 4; o; o >>= 1) {
            s2 += __shfl_xor_sync(~0u, s2, o);
            q2 += __shfl_xor_sync(~0u, q2, o);
        }
        if (!t) { sh[0] = s2; sh[1] = q2; }
    }
    __syncthreads();
    float mean = sh[0] * (1.0f / D_);
    float var  = sh[1] * (1.0f / D_) - mean * mean;
    float inv  = rsqrtf(var + 1e-6f);

    float4 sv = ((const float4*)s)[t];
    float4 bv = ((const float4*)b)[t];
    float4 o4;
    o4.x = (v.x - mean) * inv * sv.x + bv.x;
    o4.y = (v.y - mean) * inv * sv.y + bv.y;
    o4.z = (v.z - mean) * inv * sv.z + bv.z;
    o4.w = (v.w - mean) * inv * sv.w + bv.w;
    ((float4*)(y + row * (size_t)D_))[t] = o4;
}

// ---------------- SGEMM: C[M,N] = A[M,K] @ B[K,N] (+epilogue) ----------------
// 128x128x8 tile, 256 threads, 8x8 per thread. EPI: 0 none, 1 +res, 2 gelu(+bias), 3 +bias+res
template<int EPI>
__global__ __launch_bounds__(256) void sgemm128(
    const float* __restrict__ A, const float* __restrict__ Bm,
    float* __restrict__ C, int M, int N, int K,
    const float* __restrict__ bias, const float* __restrict__ res)
{
    constexpr int BM = 128, BN = 128, BK = 8;
    __shared__ float As[BK][BM];
    __shared__ float Bs[BK][BN];
    int tid  = threadIdx.x;
    int trow = tid >> 4, tcol = tid & 15;
    const float* Ab = A  + (size_t)blockIdx.y * BM * K;
    const float* Bb = Bm + (size_t)blockIdx.x * BN;
    int aRow = tid >> 1, aCol = (tid & 1) * 4;
    int bRow = tid >> 5, bCol = (tid & 31) * 4;
    float acc[8][8] = {};

    for (int k0 = 0; k0 < K; k0 += BK) {
        float4 av = *(const float4*)(Ab + (size_t)aRow * K + k0 + aCol);
        As[aCol+0][aRow] = av.x; As[aCol+1][aRow] = av.y;
        As[aCol+2][aRow] = av.z; As[aCol+3][aRow] = av.w;
        *(float4*)(&Bs[bRow][bCol]) = *(const float4*)(Bb + (size_t)(k0 + bRow) * N + bCol);
        __syncthreads();
        #pragma unroll
        for (int kk = 0; kk < BK; kk++) {
            float aR[8], bR[8];
            #pragma unroll
            for (int i = 0; i < 8; i++) aR[i] = As[kk][trow*8 + i];
            #pragma unroll
            for (int j = 0; j < 8; j++) bR[j] = Bs[kk][tcol*8 + j];
            #pragma unroll
            for (int i = 0; i < 8; i++)
                #pragma unroll
                for (int j = 0; j < 8; j++)
                    acc[i][j] = fmaf(aR[i], bR[j], acc[i][j]);
        }
        __syncthreads();
    }

    int rbase = blockIdx.y * BM + trow * 8;
    int cbase = blockIdx.x * BN + tcol * 8;
    #pragma unroll
    for (int i = 0; i < 8; i++) {
        size_t roff = (size_t)(rbase + i) * N;
        #pragma unroll
        for (int j = 0; j < 8; j += 4) {
            int c = cbase + j;
            float4 v = make_float4(acc[i][j], acc[i][j+1], acc[i][j+2], acc[i][j+3]);
            if (EPI == 1) {
                float4 rv = *(const float4*)(res + roff + c);
                v.x += rv.x; v.y += rv.y; v.z += rv.z; v.w += rv.w;
            } else if (EPI == 2) {
                float4 bv = *(const float4*)(bias + c);
                v.x = gelu_f(v.x + bv.x); v.y = gelu_f(v.y + bv.y);
                v.z = gelu_f(v.z + bv.z); v.w = gelu_f(v.w + bv.w);
            } else if (EPI == 3) {
                float4 bv = *(const float4*)(bias + c);
                float4 rv = *(const float4*)(res + roff + c);
                v.x += bv.x + rv.x; v.y += bv.y + rv.y;
                v.z += bv.z + rv.z; v.w += bv.w + rv.w;
            }
            *(float4*)(C + roff + c) = v;
        }
    }
}

// ---------------- RoPE (in place on q and k) ----------------
__global__ void rope_k(float* __restrict__ q, float* __restrict__ k)
{
    int i = blockIdx.x * blockDim.x + threadIdx.x;
    const int total = B_ * S_ * H_ * (DH_/2);
    if (i >= total) return;
    int p   = i & 31;        // pair index within head (DH/2 = 32)
    int t   = i >> 5;        // (b*S+s)*H + h
    int h   = t & 15;
    int row = t >> 4;        // b*S + s
    int s   = row & (S_ - 1);

    float freq = 1.0f / powf(10000.0f, (float)(2*p) / (float)DH_);
    float ang  = (float)s * freq;
    float sn, cs;
    sincosf(ang, &sn, &cs);

    size_t off = (size_t)row * D_ + h * DH_ + 2 * p;
    float a = q[off], b = q[off+1];
    q[off]   = a * cs - b * sn;
    q[off+1] = a * sn + b * cs;
    a = k[off]; b = k[off+1];
    k[off]   = a * cs - b * sn;
    k[off+1] = a * sn + b * cs;
}

// ---------------- scores = scale * Q @ K^T, per (b,h) ----------------
// grid: x = n tile (16), y = m tile (16), z = bh (32). Tile 128x128, K=64 in BK=8 chunks.
__global__ __launch_bounds__(256) void qk_scores_k(
    const float* __restrict__ q, const float* __restrict__ k, float* __restrict__ sc)
{
    constexpr int BM = 128, BN = 128, BK = 8;
    __shared__ float Qs[BK][BM];
    __shared__ float Ks[BK][BN];
    int bh = blockIdx.z;
    int b = bh >> 4, h = bh & 15;
    const float* qb = q + (size_t)b * S_ * D_ + h * DH_ + (size_t)blockIdx.y * BM * D_;
    const float* kb = k + (size_t)b * S_ * D_ + h * DH_ + (size_t)blockIdx.x * BN * D_;
    int tid = threadIdx.x;
    int trow = tid >> 4, tcol = tid & 15;
    int lRow = tid >> 1, lCol = (tid & 1) * 4;
    float acc[8][8] = {};

    for (int k0 = 0; k0 < DH_; k0 += BK) {
        float4 av = *(const float4*)(qb + (size_t)lRow * D_ + k0 + lCol);
        Qs[lCol+0][lRow] = av.x; Qs[lCol+1][lRow] = av.y;
        Qs[lCol+2][lRow] = av.z; Qs[lCol+3][lRow] = av.w;
        float4 bv = *(const float4*)(kb + (size_t)lRow * D_ + k0 + lCol);
        Ks[lCol+0][lRow] = bv.x; Ks[lCol+1][lRow] = bv.y;
        Ks[lCol+2][lRow] = bv.z; Ks[lCol+3][lRow] = bv.w;
        __syncthreads();
        #pragma unroll
        for (int kk = 0; kk < BK; kk++) {
            float aR[8], bR[8];
            #pragma unroll
            for (int i = 0; i < 8; i++) aR[i] = Qs[kk][trow*8 + i];
            #pragma unroll
            for (int j = 0; j < 8; j++) bR[j] = Ks[kk][tcol*8 + j];
            #pragma unroll
            for (int i = 0; i < 8; i++)
                #pragma unroll
                for (int j = 0; j < 8; j++)
                    acc[i][j] = fmaf(aR[i], bR[j], acc[i][j]);
        }
        __syncthreads();
    }

    const float scale = 0.125f;  // 1/sqrt(64)
    size_t base = ((size_t)bh * S_ + blockIdx.y * BM + trow * 8) * S_
                + blockIdx.x * BN + tcol * 8;
    #pragma unroll
    for (int i = 0; i < 8; i++) {
        #pragma unroll
        for (int j = 0; j < 8; j += 4) {
            float4 v = make_float4(acc[i][j]*scale, acc[i][j+1]*scale,
                                   acc[i][j+2]*scale, acc[i][j+3]*scale);
            *(float4*)(sc + base + (size_t)i * S_ + j) = v;
        }
    }
}

// ---------------- softmax over rows of 2048 (in place) ----------------
__global__ __launch_bounds__(256) void softmax_k(float* __restrict__ sc)
{
    size_t row = blockIdx.x;
    float4* p = (float4*)(sc + row * (size_t)S_);
    int t = threadIdx.x;
    float4 a = p[t], b = p[t + 256];

    __shared__ float sh[8];
    int lane = t & 31, w = t >> 5;

    float mx = fmaxf(fmaxf(fmaxf(a.x, a.y), fmaxf(a.z, a.w)),
                     fmaxf(fmaxf(b.x, b.y), fmaxf(b.z, b.w)));
    #pragma unroll
    for (int o = 16; o; o >>= 1) mx = fmaxf(mx, __shfl_xor_sync(~0u, mx, o));
    if (!lane) sh[w] = mx;
    __syncthreads();
    if (w == 0) {
        float m2 = (lane < 8) ? sh[lane] : -INFINITY;
        #pragma unroll
        for (int o = 4; o; o >>= 1) m2 = fmaxf(m2, __shfl_xor_sync(~0u, m2, o));
        if (!lane) sh[0] = m2;
    }
    __syncthreads();
    mx = sh[0];
    __syncthreads();

    a.x = __expf(a.x - mx); a.y = __expf(a.y - mx);
    a.z = __expf(a.z - mx); a.w = __expf(a.w - mx);
    b.x = __expf(b.x - mx); b.y = __expf(b.y - mx);
    b.z = __expf(b.z - mx); b.w = __expf(b.w - mx);

    float sum = a.x + a.y + a.z + a.w + b.x + b.y + b.z + b.w;
    #pragma unroll
    for (int o = 16; o; o >>= 1) sum += __shfl_xor_sync(~0u, sum, o);
    if (!lane) sh[w] = sum;
    __syncthreads();
    if (w == 0) {
        float s2 = (lane < 8) ? sh[lane] : 0.0f;
        #pragma unroll
        for (int o = 4; o; o >>= 1) s2 += __shfl_xor_sync(~0u, s2, o);
        if (!lane) sh[0] = s2;
    }
    __syncthreads();
    float inv = 1.0f / sh[0];

    a.x *= inv; a.y *= inv; a.z *= inv; a.w *= inv;
    b.x *= inv; b.y *= inv; b.z *= inv; b.w *= inv;
    p[t] = a; p[t + 256] = b;
}

// ---------------- ctx = P @ V, per (b,h) ----------------
// grid: y = m tile (16), z = bh (32). Tile 128(m) x 64(n), K=2048 in BK=8 chunks.
__global__ __launch_bounds__(256) void av_k(
    const float* __restrict__ sc, const float* __restrict__ v, float* __restrict__ ctx)
{
    constexpr int BM = 128, BN = 64, BK = 8;
    __shared__ float Ps[BK][BM];
    __shared__ float Vs[BK][BN];
    int bh = blockIdx.z;
    int b = bh >> 4, h = bh & 15;
    const float* pb = sc + ((size_t)bh * S_ + blockIdx.y * BM) * S_;
    const float* vb = v + (size_t)b * S_ * D_ + h * DH_;
    int tid = threadIdx.x;
    int trow = tid >> 4, tcol = tid & 15;   // trow: 8 m-rows each, tcol: 4 n-cols each
    int aRow = tid >> 1, aCol = (tid & 1) * 4;
    int bRow = tid >> 5, bCol = (tid & 31) * 2;
    float acc[8][4] = {};

    for (int k0 = 0; k0 < S_; k0 += BK) {
        float4 av2 = *(const float4*)(pb + (size_t)aRow * S_ + k0 + aCol);
        Ps[aCol+0][aRow] = av2.x; Ps[aCol+1][aRow] = av2.y;
        Ps[aCol+2][aRow] = av2.z; Ps[aCol+3][aRow] = av2.w;
        float2 bv2 = *(const float2*)(vb + (size_t)(k0 + bRow) * D_ + bCol);
        Vs[bRow][bCol] = bv2.x; Vs[bRow][bCol + 1] = bv2.y;
        __syncthreads();
        #pragma unroll
        for (int kk = 0; kk < BK; kk++) {
            float aR[8], bR[4];
            #pragma unroll
            for (int i = 0; i < 8; i++) aR[i] = Ps[kk][trow*8 + i];
            #pragma unroll
            for (int j = 0; j < 4; j++) bR[j] = Vs[kk][tcol*4 + j];
            #pragma unroll
            for (int i = 0; i < 8; i++)
                #pragma unroll
                for (int j = 0; j < 4; j++)
                    acc[i][j] = fmaf(aR[i], bR[j], acc[i][j]);
        }
        __syncthreads();
    }

    size_t base = ((size_t)b * S_ + blockIdx.y * BM + trow * 8) * D_ + h * DH_ + tcol * 4;
    #pragma unroll
    for (int i = 0; i < 8; i++) {
        float4 o4 = make_float4(acc[i][0], acc[i][1], acc[i][2], acc[i][3]);
        *(float4*)(ctx + base + (size_t)i * D_) = o4;
    }
}

// ---------------- launch ----------------
extern "C" void kernel_launch(void* const* d_in, const int* in_sizes, int n_in,
                              void* d_out, int out_size)
{
    const float* x    = (const float*)d_in[0];
    const float* ln1s = (const float*)d_in[1];
    const float* ln1b = (const float*)d_in[2];
    const float* wk   = (const float*)d_in[3];
    const float* wq   = (const float*)d_in[4];
    const float* wv   = (const float*)d_in[5];
    const float* wo   = (const float*)d_in[6];
    const float* ln2s = (const float*)d_in[7];
    const float* ln2b = (const float*)d_in[8];
    const float* w1   = (const float*)d_in[9];
    const float* b1   = (const float*)d_in[10];
    const float* w2   = (const float*)d_in[11];
    const float* b2   = (const float*)d_in[12];
    float* out = (float*)d_out;

    float *h, *q, *kb, *v, *ctx, *mlpin, *h2, *ff1, *sc;
    cudaGetSymbolAddress((void**)&h,     g_h);
    cudaGetSymbolAddress((void**)&q,     g_q);
    cudaGetSymbolAddress((void**)&kb,    g_k);
    cudaGetSymbolAddress((void**)&v,     g_v);
    cudaGetSymbolAddress((void**)&ctx,   g_ctx);
    cudaGetSymbolAddress((void**)&mlpin, g_mlpin);
    cudaGetSymbolAddress((void**)&h2,    g_h2);
    cudaGetSymbolAddress((void**)&ff1,   g_ff1);
    cudaGetSymbolAddress((void**)&sc,    g_sc);

    // LN1
    layernorm_k<<<R_, 256>>>(x, ln1s, ln1b, h);
    // QKV projections
    sgemm128<0><<<dim3(D_/128, R_/128), 256>>>(h, wq, q,  R_, D_, D_, nullptr, nullptr);
    sgemm128<0><<<dim3(D_/128, R_/128), 256>>>(h, wk, kb, R_, D_, D_, nullptr, nullptr);
    sgemm128<0><<<dim3(D_/128, R_/128), 256>>>(h, wv, v,  R_, D_, D_, nullptr, nullptr);
    // RoPE
    {
        int total = B_ * S_ * H_ * (DH_/2);
        rope_k<<<(total + 255) / 256, 256>>>(q, kb);
    }
    // attention
    qk_scores_k<<<dim3(S_/128, S_/128, B_*H_), 256>>>(q, kb, sc);
    softmax_k<<<B_*H_*S_, 256>>>(sc);
    av_k<<<dim3(1, S_/128, B_*H_), 256>>>(sc, v, ctx);
    // output projection + residual -> mlp_in
    sgemm128<1><<<dim3(D_/128, R_/128), 256>>>(ctx, wo, mlpin, R_, D_, D_, nullptr, x);
    // LN2
    layernorm_k<<<R_, 256>>>(mlpin, ln2s, ln2b, h2);
    // MLP
    sgemm128<2><<<dim3(M_/128, R_/128), 256>>>(h2,  w1, ff1, R_, M_, D_, b1, nullptr);
    sgemm128<3><<<dim3(D_/128, R_/128), 256>>>(ff1, w2, out, R_, D_, M_, b2, mlpin);
}

// round 2
// speedup vs baseline: 2.3716x; 2.3716x over previous
#include <cuda_runtime.h>
#include <math.h>
#include <stdint.h>

// Problem dims
#define B_  2
#define S_  2048
#define D_  1024
#define H_  16
#define DH_ 64
#define M_  4096
#define R_  (B_*S_)   // 4096 rows total

// ---------------- scratch (__device__ globals: allocation-free) ----------------
__device__ float g_h    [(size_t)R_*D_];
__device__ float g_q    [(size_t)R_*D_];
__device__ float g_k    [(size_t)R_*D_];
__device__ float g_v    [(size_t)R_*D_];
__device__ float g_ctx  [(size_t)R_*D_];
__device__ float g_mlpin[(size_t)R_*D_];
__device__ float g_h2   [(size_t)R_*D_];
__device__ float g_ff1  [(size_t)R_*M_];
__device__ float g_sc   [(size_t)B_*H_*S_*S_];   // 512 MB scores scratch

// ---------------- helpers ----------------
__device__ __forceinline__ float gelu_f(float x){
    const float c = 0.7978845608028654f;  // sqrt(2/pi)
    return 0.5f * x * (1.0f + tanhf(c * (x + 0.044715f * x * x * x)));
}

// round-to-nearest tf32, kept in a float register (bits only matter)
__device__ __forceinline__ float tf(float x){
    uint32_t u;
    asm("cvt.rna.tf32.f32 %0, %1;" : "=r"(u) : "f"(x));
    return __uint_as_float(u);
}

// m16n8k8 tf32 mma: D += A x B (A row-major, B col-major fragments)
__device__ __forceinline__ void mma_tf32(float* c, const uint32_t* a, const uint32_t* b){
    asm volatile(
        "mma.sync.aligned.m16n8k8.row.col.f32.tf32.tf32.f32 "
        "{%0,%1,%2,%3}, {%4,%5,%6,%7}, {%8,%9}, {%0,%1,%2,%3};"
        : "+f"(c[0]), "+f"(c[1]), "+f"(c[2]), "+f"(c[3])
        : "r"(a[0]), "r"(a[1]), "r"(a[2]), "r"(a[3]), "r"(b[0]), "r"(b[1]));
}

// ---------------- LayerNorm (one block per row, D=1024, 256 threads) ----------------
__global__ __launch_bounds__(256) void layernorm_k(
    const float* __restrict__ x, const float* __restrict__ s,
    const float* __restrict__ b, float* __restrict__ y)
{
    size_t row = blockIdx.x;
    int t = threadIdx.x;
    const float4* xr = (const float4*)(x + row * (size_t)D_);
    float4 v = xr[t];
    float sum = v.x + v.y + v.z + v.w;
    float sq  = v.x*v.x + v.y*v.y + v.z*v.z + v.w*v.w;

    __shared__ float sh[64];
    int lane = t & 31, w = t >> 5;
    #pragma unroll
    for (int o = 16; o; o >>= 1) {
        sum += __shfl_xor_sync(~0u, sum, o);
        sq  += __shfl_xor_sync(~0u, sq,  o);
    }
    if (!lane) { sh[w] = sum; sh[w + 32] = sq; }
    __syncthreads();
    if (t < 32) {
        float s2 = (t < 8) ? sh[t]      : 0.0f;
        float q2 = (t < 8) ? sh[t + 32] : 0.0f;
        #pragma unroll
        for (int o = 4; o; o >>= 1) {
            s2 += __shfl_xor_sync(~0u, s2, o);
            q2 += __shfl_xor_sync(~0u, q2, o);
        }
        if (!t) { sh[0] = s2; sh[1] = q2; }
    }
    __syncthreads();
    float mean = sh[0] * (1.0f / D_);
    float var  = sh[1] * (1.0f / D_) - mean * mean;
    float inv  = rsqrtf(var + 1e-6f);

    float4 sv = ((const float4*)s)[t];
    float4 bv = ((const float4*)b)[t];
    float4 o4;
    o4.x = (v.x - mean) * inv * sv.x + bv.x;
    o4.y = (v.y - mean) * inv * sv.y + bv.y;
    o4.z = (v.z - mean) * inv * sv.z + bv.z;
    o4.w = (v.w - mean) * inv * sv.w + bv.w;
    ((float4*)(y + row * (size_t)D_))[t] = o4;
}

// ---------------- tf32 tensor-core GEMM: C[M,N] = A[M,K] @ B[K,N] (+epilogue) ------
// 128x128x16 tile, 256 threads = 8 warps in 2(M)x4(N) grid, warp tile 64x32.
// Smem stores k-major with row stride 136 words -> conflict-free fragment loads.
// EPI: 0 none, 1 +res, 2 gelu(+bias), 3 +bias+res
template<int EPI>
__global__ __launch_bounds__(256) void gemm_tc(
    const float* __restrict__ A, const float* __restrict__ Bm,
    float* __restrict__ C, int M, int N, int K,
    const float* __restrict__ bias, const float* __restrict__ res)
{
    constexpr int BM = 128, BN = 128, BK = 16, PA = 136;
    __shared__ float As[2][BK][PA];   // [k][m]
    __shared__ float Bs[2][BK][PA];   // [k][n]
    int tid = threadIdx.x, lane = tid & 31, wid = tid >> 5;
    int g = lane >> 2, t = lane & 3;
    int wm = (wid >> 2) * 64, wn = (wid & 3) * 32;

    const float* Ab = A  + (size_t)blockIdx.y * BM * K;
    const float* Bb = Bm + (size_t)blockIdx.x * BN;

    int aRow = tid >> 1, aCol = (tid & 1) * 8;
    int bRow = tid >> 5, bCol = (tid & 31) * 4;

    float acc[4][4][4] = {};
    float4 ra0, ra1, rb0, rb1;

    // prologue: load tile 0
    ra0 = *(const float4*)(Ab + (size_t)aRow * K + aCol);
    ra1 = *(const float4*)(Ab + (size_t)aRow * K + aCol + 4);
    rb0 = *(const float4*)(Bb + (size_t)bRow * N + bCol);
    rb1 = *(const float4*)(Bb + (size_t)(bRow + 8) * N + bCol);

    const int nk = K / BK;
    for (int it = 0; it < nk; it++) {
        int buf = it & 1;
        // store current tile (tf32-converted)
        As[buf][aCol+0][aRow] = tf(ra0.x); As[buf][aCol+1][aRow] = tf(ra0.y);
        As[buf][aCol+2][aRow] = tf(ra0.z); As[buf][aCol+3][aRow] = tf(ra0.w);
        As[buf][aCol+4][aRow] = tf(ra1.x); As[buf][aCol+5][aRow] = tf(ra1.y);
        As[buf][aCol+6][aRow] = tf(ra1.z); As[buf][aCol+7][aRow] = tf(ra1.w);
        float4 c0 = make_float4(tf(rb0.x), tf(rb0.y), tf(rb0.z), tf(rb0.w));
        float4 c1 = make_float4(tf(rb1.x), tf(rb1.y), tf(rb1.z), tf(rb1.w));
        *(float4*)&Bs[buf][bRow][bCol]     = c0;
        *(float4*)&Bs[buf][bRow + 8][bCol] = c1;
        __syncthreads();

        // prefetch next tile
        if (it + 1 < nk) {
            int k0 = (it + 1) * BK;
            ra0 = *(const float4*)(Ab + (size_t)aRow * K + k0 + aCol);
            ra1 = *(const float4*)(Ab + (size_t)aRow * K + k0 + aCol + 4);
            rb0 = *(const float4*)(Bb + (size_t)(k0 + bRow) * N + bCol);
            rb1 = *(const float4*)(Bb + (size_t)(k0 + bRow + 8) * N + bCol);
        }

        // compute
        #pragma unroll
        for (int kk = 0; kk < BK; kk += 8) {
            uint32_t af[4][4], bf[4][2];
            #pragma unroll
            for (int mi = 0; mi < 4; mi++) {
                int m = wm + mi * 16 + g;
                af[mi][0] = __float_as_uint(As[buf][kk + t][m]);
                af[mi][1] = __float_as_uint(As[buf][kk + t][m + 8]);
                af[mi][2] = __float_as_uint(As[buf][kk + t + 4][m]);
                af[mi][3] = __float_as_uint(As[buf][kk + t + 4][m + 8]);
            }
            #pragma unroll
            for (int ni = 0; ni < 4; ni++) {
                int n = wn + ni * 8 + g;
                bf[ni][0] = __float_as_uint(Bs[buf][kk + t][n]);
                bf[ni][1] = __float_as_uint(Bs[buf][kk + t + 4][n]);
            }
            #pragma unroll
            for (int mi = 0; mi < 4; mi++)
                #pragma unroll
                for (int ni = 0; ni < 4; ni++)
                    mma_tf32(acc[mi][ni], af[mi], bf[ni]);
        }
        __syncthreads();
    }

    // epilogue
    #pragma unroll
    for (int mi = 0; mi < 4; mi++) {
        #pragma unroll
        for (int ci = 0; ci < 2; ci++) {
            int row = blockIdx.y * BM + wm + mi * 16 + g + ci * 8;
            size_t roff = (size_t)row * N;
            #pragma unroll
            for (int ni = 0; ni < 4; ni++) {
                int col = blockIdx.x * BN + wn + ni * 8 + 2 * t;
                float2 v = make_float2(acc[mi][ni][ci*2], acc[mi][ni][ci*2+1]);
                if (EPI == 1) {
                    float2 rv = *(const float2*)(res + roff + col);
                    v.x += rv.x; v.y += rv.y;
                } else if (EPI == 2) {
                    float2 bv = *(const float2*)(bias + col);
                    v.x = gelu_f(v.x + bv.x); v.y = gelu_f(v.y + bv.y);
                } else if (EPI == 3) {
                    float2 bv = *(const float2*)(bias + col);
                    float2 rv = *(const float2*)(res + roff + col);
                    v.x += bv.x + rv.x; v.y += bv.y + rv.y;
                }
                *(float2*)(C + roff + col) = v;
            }
        }
    }
}

// ---------------- RoPE (in place on q and k) ----------------
__global__ void rope_k(float* __restrict__ q, float* __restrict__ k)
{
    int i = blockIdx.x * blockDim.x + threadIdx.x;
    const int total = B_ * S_ * H_ * (DH_/2);
    if (i >= total) return;
    int p   = i & 31;
    int t   = i >> 5;
    int h   = t & 15;
    int row = t >> 4;
    int s   = row & (S_ - 1);

    float freq = 1.0f / powf(10000.0f, (float)(2*p) / (float)DH_);
    float ang  = (float)s * freq;
    float sn, cs;
    sincosf(ang, &sn, &cs);

    size_t off = (size_t)row * D_ + h * DH_ + 2 * p;
    float a = q[off], b = q[off+1];
    q[off]   = a * cs - b * sn;
    q[off+1] = a * sn + b * cs;
    a = k[off]; b = k[off+1];
    k[off]   = a * cs - b * sn;
    k[off+1] = a * sn + b * cs;
}

// ---------------- scores = scale * Q @ K^T, tensor cores, per (b,h) --------------
// Tile 128x128, K = DH = 64 in two 32-wide stages (keeps smem under 48KB).
__global__ __launch_bounds__(256) void qk_tc(
    const float* __restrict__ q, const float* __restrict__ k, float* __restrict__ sc)
{
    constexpr int PA = 136;
    __shared__ float Qs[32][PA];   // [d][q]
    __shared__ float Ks[32][PA];   // [d][key]
    int tid = threadIdx.x, lane = tid & 31, wid = tid >> 5;
    int g = lane >> 2, t = lane & 3;
    int wm = (wid >> 2) * 64, wn = (wid & 3) * 32;
    int bh = blockIdx.z, b = bh >> 4, h = bh & 15;
    const float* qb = q + (size_t)b * S_ * D_ + h * DH_ + (size_t)blockIdx.y * 128 * D_;
    const float* kb = k + (size_t)b * S_ * D_ + h * DH_ + (size_t)blockIdx.x * 128 * D_;

    int row = tid >> 1;
    int c0  = (tid & 1) * 16;
    float acc[4][4][4] = {};

    for (int dd = 0; dd < DH_; dd += 32) {
        // load+transpose 128 x 32 of Q and K (4 float4 per thread per matrix)
        #pragma unroll
        for (int i = 0; i < 4; i++) {
            float4 a = *(const float4*)(qb + (size_t)row * D_ + dd + c0 + i * 4);
            Qs[c0+i*4+0][row] = tf(a.x); Qs[c0+i*4+1][row] = tf(a.y);
            Qs[c0+i*4+2][row] = tf(a.z); Qs[c0+i*4+3][row] = tf(a.w);
            float4 bv = *(const float4*)(kb + (size_t)row * D_ + dd + c0 + i * 4);
            Ks[c0+i*4+0][row] = tf(bv.x); Ks[c0+i*4+1][row] = tf(bv.y);
            Ks[c0+i*4+2][row] = tf(bv.z); Ks[c0+i*4+3][row] = tf(bv.w);
        }
        __syncthreads();

        #pragma unroll
        for (int kk = 0; kk < 32; kk += 8) {
            uint32_t af[4][4], bf[4][2];
            #pragma unroll
            for (int mi = 0; mi < 4; mi++) {
                int m = wm + mi * 16 + g;
                af[mi][0] = __float_as_uint(Qs[kk + t][m]);
                af[mi][1] = __float_as_uint(Qs[kk + t][m + 8]);
                af[mi][2] = __float_as_uint(Qs[kk + t + 4][m]);
                af[mi][3] = __float_as_uint(Qs[kk + t + 4][m + 8]);
            }
            #pragma unroll
            for (int ni = 0; ni < 4; ni++) {
                int n = wn + ni * 8 + g;
                bf[ni][0] = __float_as_uint(Ks[kk + t][n]);
                bf[ni][1] = __float_as_uint(Ks[kk + t + 4][n]);
            }
            #pragma unroll
            for (int mi = 0; mi < 4; mi++)
                #pragma unroll
                for (int ni = 0; ni < 4; ni++)
                    mma_tf32(acc[mi][ni], af[mi], bf[ni]);
        }
        __syncthreads();
    }

    const float scale = 0.125f;  // 1/sqrt(64)
    #pragma unroll
    for (int mi = 0; mi < 4; mi++) {
        #pragma unroll
        for (int ci = 0; ci < 2; ci++) {
            size_t base = ((size_t)bh * S_ + blockIdx.y * 128 + wm + mi * 16 + g + ci * 8) * S_;
            #pragma unroll
            for (int ni = 0; ni < 4; ni++) {
                int col = blockIdx.x * 128 + wn + ni * 8 + 2 * t;
                float2 v = make_float2(acc[mi][ni][ci*2] * scale, acc[mi][ni][ci*2+1] * scale);
                *(float2*)(sc + base + col) = v;
            }
        }
    }
}

// ---------------- softmax over rows of 2048 (in place) ----------------
__global__ __launch_bounds__(256) void softmax_k(float* __restrict__ sc)
{
    size_t row = blockIdx.x;
    float4* p = (float4*)(sc + row * (size_t)S_);
    int t = threadIdx.x;
    float4 a = p[t], b = p[t + 256];

    __shared__ float sh[8];
    int lane = t & 31, w = t >> 5;

    float mx = fmaxf(fmaxf(fmaxf(a.x, a.y), fmaxf(a.z, a.w)),
                     fmaxf(fmaxf(b.x, b.y), fmaxf(b.z, b.w)));
    #pragma unroll
    for (int o = 16; o; o >>= 1) mx = fmaxf(mx, __shfl_xor_sync(~0u, mx, o));
    if (!lane) sh[w] = mx;
    __syncthreads();
    if (w == 0) {
        float m2 = (lane < 8) ? sh[lane] : -INFINITY;
        #pragma unroll
        for (int o = 4; o; o >>= 1) m2 = fmaxf(m2, __shfl_xor_sync(~0u, m2, o));
        if (!lane) sh[0] = m2;
    }
    __syncthreads();
    mx = sh[0];
    __syncthreads();

    a.x = __expf(a.x - mx); a.y = __expf(a.y - mx);
    a.z = __expf(a.z - mx); a.w = __expf(a.w - mx);
    b.x = __expf(b.x - mx); b.y = __expf(b.y - mx);
    b.z = __expf(b.z - mx); b.w = __expf(b.w - mx);

    float sum = a.x + a.y + a.z + a.w + b.x + b.y + b.z + b.w;
    #pragma unroll
    for (int o = 16; o; o >>= 1) sum += __shfl_xor_sync(~0u, sum, o);
    if (!lane) sh[w] = sum;
    __syncthreads();
    if (w == 0) {
        float s2 = (lane < 8) ? sh[lane] : 0.0f;
        #pragma unroll
        for (int o = 4; o; o >>= 1) s2 += __shfl_xor_sync(~0u, s2, o);
        if (!lane) sh[0] = s2;
    }
    __syncthreads();
    float inv = 1.0f / sh[0];

    a.x *= inv; a.y *= inv; a.z *= inv; a.w *= inv;
    b.x *= inv; b.y *= inv; b.z *= inv; b.w *= inv;
    p[t] = a; p[t + 256] = b;
}

// ---------------- ctx = P @ V, tensor cores, per (b,h) ----------------
// Tile 128(m) x 64(n), K = 2048 in BK=16 chunks, double-buffered.
__global__ __launch_bounds__(256) void av_tc(
    const float* __restrict__ sc, const float* __restrict__ v, float* __restrict__ ctx)
{
    constexpr int BM = 128, BN = 64, BK = 16, PA = 136, PB = 72;
    __shared__ float Ps[2][BK][PA];   // [k][q]
    __shared__ float Vs[2][BK][PB];   // [k][dh]
    int tid = threadIdx.x, lane = tid & 31, wid = tid >> 5;
    int g = lane >> 2, t = lane & 3;
    int wm = (wid >> 1) * 32, wn = (wid & 1) * 32;   // 4x2 warp grid, warp tile 32x32
    int bh = blockIdx.z, b = bh >> 4, h = bh & 15;
    const float* pb = sc + ((size_t)bh * S_ + blockIdx.y * BM) * S_;
    const float* vb = v + (size_t)b * S_ * D_ + h * DH_;

    int aRow = tid >> 1, aCol = (tid & 1) * 8;
    int bRow = tid >> 4, bCol = (tid & 15) * 4;

    float acc[2][4][4] = {};
    float4 ra0, ra1, rb0;

    ra0 = *(const float4*)(pb + (size_t)aRow * S_ + aCol);
    ra1 = *(const float4*)(pb + (size_t)aRow * S_ + aCol + 4);
    rb0 = *(const float4*)(vb + (size_t)bRow * D_ + bCol);

    const int nk = S_ / BK;
    for (int it = 0; it < nk; it++) {
        int buf = it & 1;
        Ps[buf][aCol+0][aRow] = tf(ra0.x); Ps[buf][aCol+1][aRow] = tf(ra0.y);
        Ps[buf][aCol+2][aRow] = tf(ra0.z); Ps[buf][aCol+3][aRow] = tf(ra0.w);
        Ps[buf][aCol+4][aRow] = tf(ra1.x); Ps[buf][aCol+5][aRow] = tf(ra1.y);
        Ps[buf][aCol+6][aRow] = tf(ra1.z); Ps[buf][aCol+7][aRow] = tf(ra1.w);
        float4 cb = make_float4(tf(rb0.x), tf(rb0.y), tf(rb0.z), tf(rb0.w));
        *(float4*)&Vs[buf][bRow][bCol] = cb;
        __syncthreads();

        if (it + 1 < nk) {
            int k0 = (it + 1) * BK;
            ra0 = *(const float4*)(pb + (size_t)aRow * S_ + k0 + aCol);
            ra1 = *(const float4*)(pb + (size_t)aRow * S_ + k0 + aCol + 4);
            rb0 = *(const float4*)(vb + (size_t)(k0 + bRow) * D_ + bCol);
        }

        #pragma unroll
        for (int kk = 0; kk < BK; kk += 8) {
            uint32_t af[2][4], bf[4][2];
            #pragma unroll
            for (int mi = 0; mi < 2; mi++) {
                int m = wm + mi * 16 + g;
                af[mi][0] = __float_as_uint(Ps[buf][kk + t][m]);
                af[mi][1] = __float_as_uint(Ps[buf][kk + t][m + 8]);
                af[mi][2] = __float_as_uint(Ps[buf][kk + t + 4][m]);
                af[mi][3] = __float_as_uint(Ps[buf][kk + t + 4][m + 8]);
            }
            #pragma unroll
            for (int ni = 0; ni < 4; ni++) {
                int n = wn + ni * 8 + g;
                bf[ni][0] = __float_as_uint(Vs[buf][kk + t][n]);
                bf[ni][1] = __float_as_uint(Vs[buf][kk + t + 4][n]);
            }
            #pragma unroll
            for (int mi = 0; mi < 2; mi++)
                #pragma unroll
                for (int ni = 0; ni < 4; ni++)
                    mma_tf32(acc[mi][ni], af[mi], bf[ni]);
        }
        __syncthreads();
    }

    #pragma unroll
    for (int mi = 0; mi < 2; mi++) {
        #pragma unroll
        for (int ci = 0; ci < 2; ci++) {
            int row = blockIdx.y * BM + wm + mi * 16 + g + ci * 8;
            size_t base = ((size_t)b * S_ + row) * D_ + h * DH_;
            #pragma unroll
            for (int ni = 0; ni < 4; ni++) {
                int col = wn + ni * 8 + 2 * t;
                float2 o2 = make_float2(acc[mi][ni][ci*2], acc[mi][ni][ci*2+1]);
                *(float2*)(ctx + base + col) = o2;
            }
        }
    }
}

// ---------------- launch ----------------
extern "C" void kernel_launch(void* const* d_in, const int* in_sizes, int n_in,
                              void* d_out, int out_size)
{
    const float* x    = (const float*)d_in[0];
    const float* ln1s = (const float*)d_in[1];
    const float* ln1b = (const float*)d_in[2];
    const float* wk   = (const float*)d_in[3];
    const float* wq   = (const float*)d_in[4];
    const float* wv   = (const float*)d_in[5];
    const float* wo   = (const float*)d_in[6];
    const float* ln2s = (const float*)d_in[7];
    const float* ln2b = (const float*)d_in[8];
    const float* w1   = (const float*)d_in[9];
    const float* b1   = (const float*)d_in[10];
    const float* w2   = (const float*)d_in[11];
    const float* b2   = (const float*)d_in[12];
    float* out = (float*)d_out;

    float *h, *q, *kb, *v, *ctx, *mlpin, *h2, *ff1, *sc;
    cudaGetSymbolAddress((void**)&h,     g_h);
    cudaGetSymbolAddress((void**)&q,     g_q);
    cudaGetSymbolAddress((void**)&kb,    g_k);
    cudaGetSymbolAddress((void**)&v,     g_v);
    cudaGetSymbolAddress((void**)&ctx,   g_ctx);
    cudaGetSymbolAddress((void**)&mlpin, g_mlpin);
    cudaGetSymbolAddress((void**)&h2,    g_h2);
    cudaGetSymbolAddress((void**)&ff1,   g_ff1);
    cudaGetSymbolAddress((void**)&sc,    g_sc);

    // LN1
    layernorm_k<<<R_, 256>>>(x, ln1s, ln1b, h);
    // QKV projections (tensor cores, tf32)
    gemm_tc<0><<<dim3(D_/128, R_/128), 256>>>(h, wq, q,  R_, D_, D_, nullptr, nullptr);
    gemm_tc<0><<<dim3(D_/128, R_/128), 256>>>(h, wk, kb, R_, D_, D_, nullptr, nullptr);
    gemm_tc<0><<<dim3(D_/128, R_/128), 256>>>(h, wv, v,  R_, D_, D_, nullptr, nullptr);
    // RoPE
    {
        int total = B_ * S_ * H_ * (DH_/2);
        rope_k<<<(total + 255) / 256, 256>>>(q, kb);
    }
    // attention
    qk_tc<<<dim3(S_/128, S_/128, B_*H_), 256>>>(q, kb, sc);
    softmax_k<<<B_*H_*S_, 256>>>(sc);
    av_tc<<<dim3(1, S_/128, B_*H_), 256>>>(sc, v, ctx);
    // output projection + residual -> mlp_in
    gemm_tc<1><<<dim3(D_/128, R_/128), 256>>>(ctx, wo, mlpin, R_, D_, D_, nullptr, x);
    // LN2
    layernorm_k<<<R_, 256>>>(mlpin, ln2s, ln2b, h2);
    // MLP
    gemm_tc<2><<<dim3(M_/128, R_/128), 256>>>(h2,  w1, ff1, R_, M_, D_, b1, nullptr);
    gemm_tc<3><<<dim3(D_/128, R_/128), 256>>>(ff1, w2, out, R_, D_, M_, b2, mlpin);
}

// round 7
// speedup vs baseline: 3.2624x; 1.3756x over previous
#include <cuda_runtime.h>
#include <math.h>
#include <stdint.h>

// Problem dims
#define B_  2
#define S_  2048
#define D_  1024
#define H_  16
#define DH_ 64
#define M_  4096
#define R_  (B_*S_)   // 4096 rows total

// ---------------- scratch (__device__ globals: allocation-free) ----------------
__device__ float g_h    [(size_t)R_*D_];
__device__ float g_q    [(size_t)R_*D_];
__device__ float g_k    [(size_t)R_*D_];
__device__ float g_v    [(size_t)R_*D_];
__device__ float g_ctx  [(size_t)R_*D_];
__device__ float g_mlpin[(size_t)R_*D_];
__device__ float g_h2   [(size_t)R_*D_];
__device__ float g_ff1  [(size_t)R_*M_];

// ---------------- helpers ----------------
__device__ __forceinline__ float gelu_f(float x){
    const float c = 0.7978845608028654f;  // sqrt(2/pi)
    return 0.5f * x * (1.0f + tanhf(c * (x + 0.044715f * x * x * x)));
}

__device__ __forceinline__ float tf(float x){
    uint32_t u;
    asm("cvt.rna.tf32.f32 %0, %1;" : "=r"(u) : "f"(x));
    return __uint_as_float(u);
}

__device__ __forceinline__ float ex2f(float x){
    float y; asm("ex2.approx.ftz.f32 %0, %1;" : "=f"(y) : "f"(x)); return y;
}

__device__ __forceinline__ void mma_tf32(float* c, const uint32_t* a, const uint32_t* b){
    asm volatile(
        "mma.sync.aligned.m16n8k8.row.col.f32.tf32.tf32.f32 "
        "{%0,%1,%2,%3}, {%4,%5,%6,%7}, {%8,%9}, {%0,%1,%2,%3};"
        : "+f"(c[0]), "+f"(c[1]), "+f"(c[2]), "+f"(c[3])
        : "r"(a[0]), "r"(a[1]), "r"(a[2]), "r"(a[3]), "r"(b[0]), "r"(b[1]));
}

__device__ __forceinline__ void cpa16(uint32_t dst, const void* src){
    asm volatile("cp.async.cg.shared.global [%0], [%1], 16;" :: "r"(dst), "l"(src));
}

// ---------------- LayerNorm ----------------
__global__ __launch_bounds__(256) void layernorm_k(
    const float* __restrict__ x, const float* __restrict__ s,
    const float* __restrict__ b, float* __restrict__ y)
{
    size_t row = blockIdx.x;
    int t = threadIdx.x;
    const float4* xr = (const float4*)(x + row * (size_t)D_);
    float4 v = xr[t];
    float sum = v.x + v.y + v.z + v.w;
    float sq  = v.x*v.x + v.y*v.y + v.z*v.z + v.w*v.w;

    __shared__ float sh[64];
    int lane = t & 31, w = t >> 5;
    #pragma unroll
    for (int o = 16; o; o >>= 1) {
        sum += __shfl_xor_sync(~0u, sum, o);
        sq  += __shfl_xor_sync(~0u, sq,  o);
    }
    if (!lane) { sh[w] = sum; sh[w + 32] = sq; }
    __syncthreads();
    if (t < 32) {
        float s2 = (t < 8) ? sh[t]      : 0.0f;
        float q2 = (t < 8) ? sh[t + 32] : 0.0f;
        #pragma unroll
        for (int o = 4; o; o >>= 1) {
            s2 += __shfl_xor_sync(~0u, s2, o);
            q2 += __shfl_xor_sync(~0u, q2, o);
        }
        if (!t) { sh[0] = s2; sh[1] = q2; }
    }
    __syncthreads();
    float mean = sh[0] * (1.0f / D_);
    float var  = sh[1] * (1.0f / D_) - mean * mean;
    float inv  = rsqrtf(var + 1e-6f);

    float4 sv = ((const float4*)s)[t];
    float4 bv = ((const float4*)b)[t];
    float4 o4;
    o4.x = (v.x - mean) * inv * sv.x + bv.x;
    o4.y = (v.y - mean) * inv * sv.y + bv.y;
    o4.z = (v.z - mean) * inv * sv.z + bv.z;
    o4.w = (v.w - mean) * inv * sv.w + bv.w;
    ((float4*)(y + row * (size_t)D_))[t] = o4;
}

// ---------------- tf32 tensor-core GEMM ----------------
template<int EPI>
__global__ __launch_bounds__(256, 2) void gemm_tc(
    const float* __restrict__ A, const float* __restrict__ Bm,
    float* __restrict__ C, int M, int N, int K,
    const float* __restrict__ bias, const float* __restrict__ res)
{
    constexpr int BM = 128, BN = 128, BK = 16, PA = 136;
    __shared__ float As[2][BK][PA];
    __shared__ float Bs[2][BK][PA];
    int tid = threadIdx.x, lane = tid & 31, wid = tid >> 5;
    int g = lane >> 2, t = lane & 3;
    int wm = (wid >> 2) * 64, wn = (wid & 3) * 32;

    const float* Ab = A  + (size_t)blockIdx.y * BM * K;
    const float* Bb = Bm + (size_t)blockIdx.x * BN;

    int aRow = tid >> 1, aCol = (tid & 1) * 8;
    int bRow = tid >> 5, bCol = (tid & 31) * 4;

    float acc[4][4][4] = {};
    float4 ra0, ra1, rb0, rb1;

    ra0 = *(const float4*)(Ab + (size_t)aRow * K + aCol);
    ra1 = *(const float4*)(Ab + (size_t)aRow * K + aCol + 4);
    rb0 = *(const float4*)(Bb + (size_t)bRow * N + bCol);
    rb1 = *(const float4*)(Bb + (size_t)(bRow + 8) * N + bCol);

    const int nk = K / BK;
    for (int it = 0; it < nk; it++) {
        int buf = it & 1;
        As[buf][aCol+0][aRow] = tf(ra0.x); As[buf][aCol+1][aRow] = tf(ra0.y);
        As[buf][aCol+2][aRow] = tf(ra0.z); As[buf][aCol+3][aRow] = tf(ra0.w);
        As[buf][aCol+4][aRow] = tf(ra1.x); As[buf][aCol+5][aRow] = tf(ra1.y);
        As[buf][aCol+6][aRow] = tf(ra1.z); As[buf][aCol+7][aRow] = tf(ra1.w);
        float4 c0 = make_float4(tf(rb0.x), tf(rb0.y), tf(rb0.z), tf(rb0.w));
        float4 c1 = make_float4(tf(rb1.x), tf(rb1.y), tf(rb1.z), tf(rb1.w));
        *(float4*)&Bs[buf][bRow][bCol]     = c0;
        *(float4*)&Bs[buf][bRow + 8][bCol] = c1;
        __syncthreads();

        if (it + 1 < nk) {
            int k0 = (it + 1) * BK;
            ra0 = *(const float4*)(Ab + (size_t)aRow * K + k0 + aCol);
            ra1 = *(const float4*)(Ab + (size_t)aRow * K + k0 + aCol + 4);
            rb0 = *(const float4*)(Bb + (size_t)(k0 + bRow) * N + bCol);
            rb1 = *(const float4*)(Bb + (size_t)(k0 + bRow + 8) * N + bCol);
        }

        #pragma unroll
        for (int kk = 0; kk < BK; kk += 8) {
            uint32_t af[4][4], bf[4][2];
            #pragma unroll
            for (int mi = 0; mi < 4; mi++) {
                int m = wm + mi * 16 + g;
                af[mi][0] = __float_as_uint(As[buf][kk + t][m]);
                af[mi][1] = __float_as_uint(As[buf][kk + t][m + 8]);
                af[mi][2] = __float_as_uint(As[buf][kk + t + 4][m]);
                af[mi][3] = __float_as_uint(As[buf][kk + t + 4][m + 8]);
            }
            #pragma unroll
            for (int ni = 0; ni < 4; ni++) {
                int n = wn + ni * 8 + g;
                bf[ni][0] = __float_as_uint(Bs[buf][kk + t][n]);
                bf[ni][1] = __float_as_uint(Bs[buf][kk + t + 4][n]);
            }
            #pragma unroll
            for (int mi = 0; mi < 4; mi++)
                #pragma unroll
                for (int ni = 0; ni < 4; ni++)
                    mma_tf32(acc[mi][ni], af[mi], bf[ni]);
        }
        // NOTE: no trailing barrier — next iter stores into the other buffer,
        // whose readers all passed the barrier above.
    }

    #pragma unroll
    for (int mi = 0; mi < 4; mi++) {
        #pragma unroll
        for (int ci = 0; ci < 2; ci++) {
            int row = blockIdx.y * BM + wm + mi * 16 + g + ci * 8;
            size_t roff = (size_t)row * N;
            #pragma unroll
            for (int ni = 0; ni < 4; ni++) {
                int col = blockIdx.x * BN + wn + ni * 8 + 2 * t;
                float2 v = make_float2(acc[mi][ni][ci*2], acc[mi][ni][ci*2+1]);
                if (EPI == 1) {
                    float2 rv = *(const float2*)(res + roff + col);
                    v.x += rv.x; v.y += rv.y;
                } else if (EPI == 2) {
                    float2 bv = *(const float2*)(bias + col);
                    v.x = gelu_f(v.x + bv.x); v.y = gelu_f(v.y + bv.y);
                } else if (EPI == 3) {
                    float2 bv = *(const float2*)(bias + col);
                    float2 rv = *(const float2*)(res + roff + col);
                    v.x += bv.x + rv.x; v.y += bv.y + rv.y;
                }
                *(float2*)(C + roff + col) = v;
            }
        }
    }
}

// ---------------- RoPE ----------------
__global__ void rope_k(float* __restrict__ q, float* __restrict__ k)
{
    int i = blockIdx.x * blockDim.x + threadIdx.x;
    const int total = B_ * S_ * H_ * (DH_/2);
    if (i >= total) return;
    int p   = i & 31;
    int t   = i >> 5;
    int h   = t & 15;
    int row = t >> 4;
    int s   = row & (S_ - 1);

    float freq = 1.0f / powf(10000.0f, (float)(2*p) / (float)DH_);
    float ang  = (float)s * freq;
    float sn, cs;
    sincosf(ang, &sn, &cs);

    size_t off = (size_t)row * D_ + h * DH_ + 2 * p;
    float a = q[off], b = q[off+1];
    q[off]   = a * cs - b * sn;
    q[off+1] = a * sn + b * cs;
    a = k[off]; b = k[off+1];
    k[off]   = a * cs - b * sn;
    k[off+1] = a * sn + b * cs;
}

// ---------------- flash attention ----------------
// One block = (bh, 128-row q tile). 256 threads, 8 warps, warp owns 16 q rows.
// smem: Ks[2][128][68] (K, kv-major), Vs[2][128][72], Ps[128][136] (P transposed [kv][q]).
#define KPAD 68
#define VPAD 72
#define PPAD 136
#define KS_FLOATS (2*128*KPAD)
#define VS_FLOATS (2*128*VPAD)
#define FLASH_SMEM ((KS_FLOATS + VS_FLOATS + 128*PPAD) * 4)

__global__ __launch_bounds__(256) void flash_k(
    const float* __restrict__ q, const float* __restrict__ k,
    const float* __restrict__ v, float* __restrict__ ctx)
{
    extern __shared__ float sm[];
    float* Ks = sm;
    float* Vs = sm + KS_FLOATS;
    float* Ps = sm + KS_FLOATS + VS_FLOATS;
    uint32_t ks_b = (uint32_t)__cvta_generic_to_shared(Ks);
    uint32_t vs_b = (uint32_t)__cvta_generic_to_shared(Vs);

    int tid = threadIdx.x, lane = tid & 31, wid = tid >> 5;
    int g = lane >> 2, t = lane & 3;
    int bh = blockIdx.y, b = bh >> 4, h = bh & 15;
    int q0 = blockIdx.x * 128;
    const float* qb = q + (size_t)b * S_ * D_ + h * DH_;
    const float* kb = k + (size_t)b * S_ * D_ + h * DH_;
    const float* vb = v + (size_t)b * S_ * D_ + h * DH_;

    // stage Q tile into Ps transposed [d][q]
    {
        int row = tid >> 1, c0 = (tid & 1) * 32;
        const float* src = qb + (size_t)(q0 + row) * D_ + c0;
        #pragma unroll
        for (int i = 0; i < 8; i++) {
            float4 a = *(const float4*)(src + i * 4);
            Ps[(c0+i*4+0)*PPAD + row] = a.x;
            Ps[(c0+i*4+1)*PPAD + row] = a.y;
            Ps[(c0+i*4+2)*PPAD + row] = a.z;
            Ps[(c0+i*4+3)*PPAD + row] = a.w;
        }
    }

    // prologue: async-load kv tile 0 into buf 0
    {
        #pragma unroll
        for (int j = 0; j < 8; j++) {
            int id = tid + 256 * j;
            int r = id >> 4, c = id & 15;
            const float* gk = kb + (size_t)r * D_ + c * 4;
            const float* gv = vb + (size_t)r * D_ + c * 4;
            cpa16(ks_b + (r * KPAD + c * 4) * 4, gk);
            cpa16(vs_b + (r * VPAD + c * 4) * 4, gv);
        }
        asm volatile("cp.async.commit_group;");
    }
    __syncthreads();

    // Q fragments (per warp: 16 rows x 64 d)
    int m0 = wid * 16 + g;
    uint32_t qf[8][4];
    #pragma unroll
    for (int ks = 0; ks < 8; ks++) {
        qf[ks][0] = __float_as_uint(Ps[(8*ks+t  )*PPAD + m0    ]);
        qf[ks][1] = __float_as_uint(Ps[(8*ks+t  )*PPAD + m0 + 8]);
        qf[ks][2] = __float_as_uint(Ps[(8*ks+t+4)*PPAD + m0    ]);
        qf[ks][3] = __float_as_uint(Ps[(8*ks+t+4)*PPAD + m0 + 8]);
    }

    float m2[2] = {-1e30f, -1e30f};
    float l[2]  = {0.0f, 0.0f};
    float ao[8][4] = {};
    const float cs = 0.125f * 1.4426950408889634f;   // 1/sqrt(DH) * log2(e)

    const int NT = S_ / 128;
    for (int it = 0; it < NT; it++) {
        int buf = it & 1;
        asm volatile("cp.async.wait_group 0;");
        __syncthreads();

        if (it + 1 < NT) {
            int kv0 = (it + 1) * 128;
            uint32_t kd = ks_b + (buf ^ 1) * 128 * KPAD * 4;
            uint32_t vd = vs_b + (buf ^ 1) * 128 * VPAD * 4;
            #pragma unroll
            for (int j = 0; j < 8; j++) {
                int id = tid + 256 * j;
                int r = id >> 4, c = id & 15;
                cpa16(kd + (r * KPAD + c * 4) * 4, kb + (size_t)(kv0 + r) * D_ + c * 4);
                cpa16(vd + (r * VPAD + c * 4) * 4, vb + (size_t)(kv0 + r) * D_ + c * 4);
            }
            asm volatile("cp.async.commit_group;");
        }

        const float* Kt = Ks + buf * 128 * KPAD;
        const float* Vt = Vs + buf * 128 * VPAD;

        // S = Q @ K^T  (warp: 16 x 128)
        float s[16][4] = {};
        #pragma unroll
        for (int ni = 0; ni < 16; ni++) {
            #pragma unroll
            for (int ks = 0; ks < 8; ks++) {
                uint32_t bf[2];
                bf[0] = __float_as_uint(Kt[(8*ni+g)*KPAD + 8*ks + t    ]);
                bf[1] = __float_as_uint(Kt[(8*ni+g)*KPAD + 8*ks + t + 4]);
                mma_tf32(s[ni], qf[ks], bf);
            }
        }

        // online softmax (rows g, g+8; cols spread over t lanes)
        float mx0 = -1e30f, mx1 = -1e30f;
        #pragma unroll
        for (int ni = 0; ni < 16; ni++) {
            mx0 = fmaxf(mx0, fmaxf(s[ni][0], s[ni][1]));
            mx1 = fmaxf(mx1, fmaxf(s[ni][2], s[ni][3]));
        }
        mx0 = fmaxf(mx0, __shfl_xor_sync(~0u, mx0, 1));
        mx0 = fmaxf(mx0, __shfl_xor_sync(~0u, mx0, 2));
        mx1 = fmaxf(mx1, __shfl_xor_sync(~0u, mx1, 1));
        mx1 = fmaxf(mx1, __shfl_xor_sync(~0u, mx1, 2));
        float nm0 = fmaxf(m2[0], mx0 * cs);
        float nm1 = fmaxf(m2[1], mx1 * cs);
        float cr0 = ex2f(m2[0] - nm0);
        float cr1 = ex2f(m2[1] - nm1);
        m2[0] = nm0; m2[1] = nm1;

        float sum0 = 0.0f, sum1 = 0.0f;
        #pragma unroll
        for (int ni = 0; ni < 16; ni++) {
            s[ni][0] = ex2f(fmaf(s[ni][0], cs, -nm0));
            s[ni][1] = ex2f(fmaf(s[ni][1], cs, -nm0));
            s[ni][2] = ex2f(fmaf(s[ni][2], cs, -nm1));
            s[ni][3] = ex2f(fmaf(s[ni][3], cs, -nm1));
            sum0 += s[ni][0] + s[ni][1];
            sum1 += s[ni][2] + s[ni][3];
        }
        sum0 += __shfl_xor_sync(~0u, sum0, 1);
        sum0 += __shfl_xor_sync(~0u, sum0, 2);
        sum1 += __shfl_xor_sync(~0u, sum1, 1);
        sum1 += __shfl_xor_sync(~0u, sum1, 2);
        l[0] = l[0] * cr0 + sum0;
        l[1] = l[1] * cr1 + sum1;

        #pragma unroll
        for (int ni = 0; ni < 8; ni++) {
            ao[ni][0] *= cr0; ao[ni][1] *= cr0;
            ao[ni][2] *= cr1; ao[ni][3] *= cr1;
        }

        // store P to Ps[kv][q] (warp-local q columns)
        #pragma unroll
        for (int ni = 0; ni < 16; ni++) {
            int col = 8 * ni + 2 * t;
            Ps[(col    )*PPAD + m0    ] = s[ni][0];
            Ps[(col + 1)*PPAD + m0    ] = s[ni][1];
            Ps[(col    )*PPAD + m0 + 8] = s[ni][2];
            Ps[(col + 1)*PPAD + m0 + 8] = s[ni][3];
        }
        __syncwarp();

        // O += P @ V  (warp: 16 x 64, k = 128)
        #pragma unroll
        for (int kst = 0; kst < 16; kst++) {
            uint32_t af[4];
            af[0] = __float_as_uint(Ps[(8*kst+t  )*PPAD + m0    ]);
            af[1] = __float_as_uint(Ps[(8*kst+t  )*PPAD + m0 + 8]);
            af[2] = __float_as_uint(Ps[(8*kst+t+4)*PPAD + m0    ]);
            af[3] = __float_as_uint(Ps[(8*kst+t+4)*PPAD + m0 + 8]);
            #pragma unroll
            for (int ni = 0; ni < 8; ni++) {
                uint32_t bf[2];
                bf[0] = __float_as_uint(Vt[(8*kst+t  )*VPAD + 8*ni + g]);
                bf[1] = __float_as_uint(Vt[(8*kst+t+4)*VPAD + 8*ni + g]);
                mma_tf32(ao[ni], af, bf);
            }
        }
        // next iteration's barrier (after wait_group) protects Kt/Vt reuse
    }

    // epilogue: normalize and write ctx
    float inv0 = 1.0f / l[0], inv1 = 1.0f / l[1];
    size_t base0 = ((size_t)b * S_ + q0 + m0) * D_ + h * DH_;
    size_t base1 = base0 + 8 * (size_t)D_;
    #pragma unroll
    for (int ni = 0; ni < 8; ni++) {
        int col = 8 * ni + 2 * t;
        float2 o0 = make_float2(ao[ni][0] * inv0, ao[ni][1] * inv0);
        float2 o1 = make_float2(ao[ni][2] * inv1, ao[ni][3] * inv1);
        *(float2*)(ctx + base0 + col) = o0;
        *(float2*)(ctx + base1 + col) = o1;
    }
}

// ---------------- launch ----------------
extern "C" void kernel_launch(void* const* d_in, const int* in_sizes, int n_in,
                              void* d_out, int out_size)
{
    const float* x    = (const float*)d_in[0];
    const float* ln1s = (const float*)d_in[1];
    const float* ln1b = (const float*)d_in[2];
    const float* wk   = (const float*)d_in[3];
    const float* wq   = (const float*)d_in[4];
    const float* wv   = (const float*)d_in[5];
    const float* wo   = (const float*)d_in[6];
    const float* ln2s = (const float*)d_in[7];
    const float* ln2b = (const float*)d_in[8];
    const float* w1   = (const float*)d_in[9];
    const float* b1   = (const float*)d_in[10];
    const float* w2   = (const float*)d_in[11];
    const float* b2   = (const float*)d_in[12];
    float* out = (float*)d_out;

    float *h, *q, *kb, *v, *ctx, *mlpin, *h2, *ff1;
    cudaGetSymbolAddress((void**)&h,     g_h);
    cudaGetSymbolAddress((void**)&q,     g_q);
    cudaGetSymbolAddress((void**)&kb,    g_k);
    cudaGetSymbolAddress((void**)&v,     g_v);
    cudaGetSymbolAddress((void**)&ctx,   g_ctx);
    cudaGetSymbolAddress((void**)&mlpin, g_mlpin);
    cudaGetSymbolAddress((void**)&h2,    g_h2);
    cudaGetSymbolAddress((void**)&ff1,   g_ff1);

    cudaFuncSetAttribute(flash_k, cudaFuncAttributeMaxDynamicSharedMemorySize, FLASH_SMEM);

    layernorm_k<<<R_, 256>>>(x, ln1s, ln1b, h);
    gemm_tc<0><<<dim3(D_/128, R_/128), 256>>>(h, wq, q,  R_, D_, D_, nullptr, nullptr);
    gemm_tc<0><<<dim3(D_/128, R_/128), 256>>>(h, wk, kb, R_, D_, D_, nullptr, nullptr);
    gemm_tc<0><<<dim3(D_/128, R_/128), 256>>>(h, wv, v,  R_, D_, D_, nullptr, nullptr);
    {
        int total = B_ * S_ * H_ * (DH_/2);
        rope_k<<<(total + 255) / 256, 256>>>(q, kb);
    }
    flash_k<<<dim3(S_/128, B_*H_), 256, FLASH_SMEM>>>(q, kb, v, ctx);
    gemm_tc<1><<<dim3(D_/128, R_/128), 256>>>(ctx, wo, mlpin, R_, D_, D_, nullptr, x);
    layernorm_k<<<R_, 256>>>(mlpin, ln2s, ln2b, h2);
    gemm_tc<2><<<dim3(M_/128, R_/128), 256>>>(h2,  w1, ff1, R_, M_, D_, b1, nullptr);
    gemm_tc<3><<<dim3(D_/128, R_/128), 256>>>(ff1, w2, out, R_, D_, M_, b2, mlpin);
}

// round 8
// speedup vs baseline: 3.5639x; 1.0924x over previous
#include <cuda_runtime.h>
#include <math.h>
#include <stdint.h>

// Problem dims
#define B_  2
#define S_  2048
#define D_  1024
#define H_  16
#define DH_ 64
#define M_  4096
#define R_  (B_*S_)   // 4096 rows total

// ---------------- scratch (__device__ globals: allocation-free) ----------------
__device__ float g_h    [(size_t)R_*D_];
__device__ float g_q    [(size_t)R_*D_];
__device__ float g_k    [(size_t)R_*D_];
__device__ float g_v    [(size_t)R_*D_];
__device__ float g_ctx  [(size_t)R_*D_];
__device__ float g_mlpin[(size_t)R_*D_];
__device__ float g_h2   [(size_t)R_*D_];
__device__ float g_ff1  [(size_t)R_*M_];

// ---------------- helpers ----------------
__device__ __forceinline__ float gelu_f(float x){
    const float c = 0.7978845608028654f;  // sqrt(2/pi)
    return 0.5f * x * (1.0f + tanhf(c * (x + 0.044715f * x * x * x)));
}

__device__ __forceinline__ float ex2f(float x){
    float y; asm("ex2.approx.ftz.f32 %0, %1;" : "=f"(y) : "f"(x)); return y;
}

__device__ __forceinline__ void mma_tf32(float* c, const uint32_t* a, const uint32_t* b){
    asm volatile(
        "mma.sync.aligned.m16n8k8.row.col.f32.tf32.tf32.f32 "
        "{%0,%1,%2,%3}, {%4,%5,%6,%7}, {%8,%9}, {%0,%1,%2,%3};"
        : "+f"(c[0]), "+f"(c[1]), "+f"(c[2]), "+f"(c[3])
        : "r"(a[0]), "r"(a[1]), "r"(a[2]), "r"(a[3]), "r"(b[0]), "r"(b[1]));
}

__device__ __forceinline__ void cpa16(uint32_t dst, const void* src){
    asm volatile("cp.async.cg.shared.global [%0], [%1], 16;" :: "r"(dst), "l"(src));
}

// ---------------- LayerNorm ----------------
__global__ __launch_bounds__(256) void layernorm_k(
    const float* __restrict__ x, const float* __restrict__ s,
    const float* __restrict__ b, float* __restrict__ y)
{
    size_t row = blockIdx.x;
    int t = threadIdx.x;
    const float4* xr = (const float4*)(x + row * (size_t)D_);
    float4 v = xr[t];
    float sum = v.x + v.y + v.z + v.w;
    float sq  = v.x*v.x + v.y*v.y + v.z*v.z + v.w*v.w;

    __shared__ float sh[64];
    int lane = t & 31, w = t >> 5;
    #pragma unroll
    for (int o = 16; o; o >>= 1) {
        sum += __shfl_xor_sync(~0u, sum, o);
        sq  += __shfl_xor_sync(~0u, sq,  o);
    }
    if (!lane) { sh[w] = sum; sh[w + 32] = sq; }
    __syncthreads();
    if (t < 32) {
        float s2 = (t < 8) ? sh[t]      : 0.0f;
        float q2 = (t < 8) ? sh[t + 32] : 0.0f;
        #pragma unroll
        for (int o = 4; o; o >>= 1) {
            s2 += __shfl_xor_sync(~0u, s2, o);
            q2 += __shfl_xor_sync(~0u, q2, o);
        }
        if (!t) { sh[0] = s2; sh[1] = q2; }
    }
    __syncthreads();
    float mean = sh[0] * (1.0f / D_);
    float var  = sh[1] * (1.0f / D_) - mean * mean;
    float inv  = rsqrtf(var + 1e-6f);

    float4 sv = ((const float4*)s)[t];
    float4 bv = ((const float4*)b)[t];
    float4 o4;
    o4.x = (v.x - mean) * inv * sv.x + bv.x;
    o4.y = (v.y - mean) * inv * sv.y + bv.y;
    o4.z = (v.z - mean) * inv * sv.z + bv.z;
    o4.w = (v.w - mean) * inv * sv.w + bv.w;
    ((float4*)(y + row * (size_t)D_))[t] = o4;
}

// ---------------- tf32 tensor-core GEMM, cp.async 3-stage pipeline ----------------
// 128x128x16 tile, 256 threads = 8 warps (2x4), warp tile 64x32.
// A in smem row-major [m][k] stride 20 (conflict-free a-frags);
// B in smem [k][n] stride 136 (conflict-free b-frags).
// No explicit tf32 cvt: HMMA.tf32 truncates fp32 operands in HW.
#define GA_PAD 20
#define GB_PAD 136
#define GA_STG (128*GA_PAD)   // 2560 floats
#define GB_STG (16*GB_PAD)    // 2176 floats
#define GEMM_SMEM ((3*GA_STG + 3*GB_STG)*4)

template<int EPI>
__global__ __launch_bounds__(256, 2) void gemm_tc(
    const float* __restrict__ A, const float* __restrict__ Bm,
    float* __restrict__ C, int M, int N, int K,
    const float* __restrict__ bias, const float* __restrict__ res)
{
    constexpr int BM = 128, BN = 128, BK = 16;
    extern __shared__ float sm[];
    float* As = sm;                 // [3][128][20]
    float* Bs = sm + 3 * GA_STG;    // [3][16][136]
    uint32_t as_b = (uint32_t)__cvta_generic_to_shared(As);
    uint32_t bs_b = (uint32_t)__cvta_generic_to_shared(Bs);

    int tid = threadIdx.x, lane = tid & 31, wid = tid >> 5;
    int g = lane >> 2, t = lane & 3;
    int wm = (wid >> 2) * 64, wn = (wid & 3) * 32;

    const float* Ab = A  + (size_t)blockIdx.y * BM * K;
    const float* Bb = Bm + (size_t)blockIdx.x * BN;

    // cp.async maps: A: 128 rows x 4 chunks(16B); B: 16 rows x 32 chunks(16B)
    int ar  = tid >> 1;          // 0..127
    int ac0 = (tid & 1) * 2;     // chunks ac0, ac0+1
    int br  = tid >> 4;          // 0..15
    int bc0 = tid & 15;          // chunks bc0, bc0+16

    float acc[4][4][4] = {};
    const int nk = K / BK;

    // prologue: stages 0,1
    #pragma unroll
    for (int p = 0; p < 2; p++) {
        int k0 = p * BK;
        uint32_t ad = as_b + (p * GA_STG + ar * GA_PAD) * 4;
        const float* ag = Ab + (size_t)ar * K + k0;
        cpa16(ad + (ac0    ) * 16, ag + (ac0    ) * 4);
        cpa16(ad + (ac0 + 1) * 16, ag + (ac0 + 1) * 4);
        uint32_t bd = bs_b + (p * GB_STG + br * GB_PAD) * 4;
        const float* bg = Bb + (size_t)(k0 + br) * N;
        cpa16(bd + (bc0     ) * 16, bg + (bc0     ) * 4);
        cpa16(bd + (bc0 + 16) * 16, bg + (bc0 + 16) * 4);
        asm volatile("cp.async.commit_group;");
    }

    for (int it = 0; it < nk; it++) {
        int st = it % 3;
        if (it + 1 < nk) asm volatile("cp.async.wait_group 1;");
        else             asm volatile("cp.async.wait_group 0;");
        __syncthreads();

        if (it + 2 < nk) {
            int s2 = (it + 2) % 3;
            int k0 = (it + 2) * BK;
            uint32_t ad = as_b + (s2 * GA_STG + ar * GA_PAD) * 4;
            const float* ag = Ab + (size_t)ar * K + k0;
            cpa16(ad + (ac0    ) * 16, ag + (ac0    ) * 4);
            cpa16(ad + (ac0 + 1) * 16, ag + (ac0 + 1) * 4);
            uint32_t bd = bs_b + (s2 * GB_STG + br * GB_PAD) * 4;
            const float* bg = Bb + (size_t)(k0 + br) * N;
            cpa16(bd + (bc0     ) * 16, bg + (bc0     ) * 4);
            cpa16(bd + (bc0 + 16) * 16, bg + (bc0 + 16) * 4);
            asm volatile("cp.async.commit_group;");
        }

        const float* Asx = As + st * GA_STG;
        const float* Bsx = Bs + st * GB_STG;
        #pragma unroll
        for (int kk = 0; kk < BK; kk += 8) {
            uint32_t af[4][4], bf[4][2];
            #pragma unroll
            for (int mi = 0; mi < 4; mi++) {
                int m = wm + mi * 16 + g;
                af[mi][0] = __float_as_uint(Asx[(m    ) * GA_PAD + kk + t    ]);
                af[mi][1] = __float_as_uint(Asx[(m + 8) * GA_PAD + kk + t    ]);
                af[mi][2] = __float_as_uint(Asx[(m    ) * GA_PAD + kk + t + 4]);
                af[mi][3] = __float_as_uint(Asx[(m + 8) * GA_PAD + kk + t + 4]);
            }
            #pragma unroll
            for (int ni = 0; ni < 4; ni++) {
                int n = wn + ni * 8 + g;
                bf[ni][0] = __float_as_uint(Bsx[(kk + t    ) * GB_PAD + n]);
                bf[ni][1] = __float_as_uint(Bsx[(kk + t + 4) * GB_PAD + n]);
            }
            #pragma unroll
            for (int mi = 0; mi < 4; mi++)
                #pragma unroll
                for (int ni = 0; ni < 4; ni++)
                    mma_tf32(acc[mi][ni], af[mi], bf[ni]);
        }
        // no trailing barrier: next iter's wait+syncthreads precedes the only
        // writes (into stage (it+3)%3 == st) after all readers are done.
    }

    #pragma unroll
    for (int mi = 0; mi < 4; mi++) {
        #pragma unroll
        for (int ci = 0; ci < 2; ci++) {
            int row = blockIdx.y * BM + wm + mi * 16 + g + ci * 8;
            size_t roff = (size_t)row * N;
            #pragma unroll
            for (int ni = 0; ni < 4; ni++) {
                int col = blockIdx.x * BN + wn + ni * 8 + 2 * t;
                float2 v = make_float2(acc[mi][ni][ci*2], acc[mi][ni][ci*2+1]);
                if (EPI == 1) {
                    float2 rv = *(const float2*)(res + roff + col);
                    v.x += rv.x; v.y += rv.y;
                } else if (EPI == 2) {
                    float2 bv = *(const float2*)(bias + col);
                    v.x = gelu_f(v.x + bv.x); v.y = gelu_f(v.y + bv.y);
                } else if (EPI == 3) {
                    float2 bv = *(const float2*)(bias + col);
                    float2 rv = *(const float2*)(res + roff + col);
                    v.x += bv.x + rv.x; v.y += bv.y + rv.y;
                }
                *(float2*)(C + roff + col) = v;
            }
        }
    }
}

// ---------------- RoPE ----------------
__global__ void rope_k(float* __restrict__ q, float* __restrict__ k)
{
    int i = blockIdx.x * blockDim.x + threadIdx.x;
    const int total = B_ * S_ * H_ * (DH_/2);
    if (i >= total) return;
    int p   = i & 31;
    int t   = i >> 5;
    int h   = t & 15;
    int row = t >> 4;
    int s   = row & (S_ - 1);

    float freq = 1.0f / powf(10000.0f, (float)(2*p) / (float)DH_);
    float ang  = (float)s * freq;
    float sn, cs;
    sincosf(ang, &sn, &cs);

    size_t off = (size_t)row * D_ + h * DH_ + 2 * p;
    float a = q[off], b = q[off+1];
    q[off]   = a * cs - b * sn;
    q[off+1] = a * sn + b * cs;
    a = k[off]; b = k[off+1];
    k[off]   = a * cs - b * sn;
    k[off+1] = a * sn + b * cs;
}

// ---------------- flash attention ----------------
#define KPAD 68
#define VPAD 72
#define PPAD 136
#define KS_FLOATS (2*128*KPAD)
#define VS_FLOATS (2*128*VPAD)
#define FLASH_SMEM ((KS_FLOATS + VS_FLOATS + 128*PPAD) * 4)

__global__ __launch_bounds__(256) void flash_k(
    const float* __restrict__ q, const float* __restrict__ k,
    const float* __restrict__ v, float* __restrict__ ctx)
{
    extern __shared__ float sm[];
    float* Ks = sm;
    float* Vs = sm + KS_FLOATS;
    float* Ps = sm + KS_FLOATS + VS_FLOATS;
    uint32_t ks_b = (uint32_t)__cvta_generic_to_shared(Ks);
    uint32_t vs_b = (uint32_t)__cvta_generic_to_shared(Vs);

    int tid = threadIdx.x, lane = tid & 31, wid = tid >> 5;
    int g = lane >> 2, t = lane & 3;
    int bh = blockIdx.y, b = bh >> 4, h = bh & 15;
    int q0 = blockIdx.x * 128;
    const float* qb = q + (size_t)b * S_ * D_ + h * DH_;
    const float* kb = k + (size_t)b * S_ * D_ + h * DH_;
    const float* vb = v + (size_t)b * S_ * D_ + h * DH_;

    {
        int row = tid >> 1, c0 = (tid & 1) * 32;
        const float* src = qb + (size_t)(q0 + row) * D_ + c0;
        #pragma unroll
        for (int i = 0; i < 8; i++) {
            float4 a = *(const float4*)(src + i * 4);
            Ps[(c0+i*4+0)*PPAD + row] = a.x;
            Ps[(c0+i*4+1)*PPAD + row] = a.y;
            Ps[(c0+i*4+2)*PPAD + row] = a.z;
            Ps[(c0+i*4+3)*PPAD + row] = a.w;
        }
    }

    {
        #pragma unroll
        for (int j = 0; j < 8; j++) {
            int id = tid + 256 * j;
            int r = id >> 4, c = id & 15;
            const float* gk = kb + (size_t)r * D_ + c * 4;
            const float* gv = vb + (size_t)r * D_ + c * 4;
            cpa16(ks_b + (r * KPAD + c * 4) * 4, gk);
            cpa16(vs_b + (r * VPAD + c * 4) * 4, gv);
        }
        asm volatile("cp.async.commit_group;");
    }
    __syncthreads();

    int m0 = wid * 16 + g;
    uint32_t qf[8][4];
    #pragma unroll
    for (int ks = 0; ks < 8; ks++) {
        qf[ks][0] = __float_as_uint(Ps[(8*ks+t  )*PPAD + m0    ]);
        qf[ks][1] = __float_as_uint(Ps[(8*ks+t  )*PPAD + m0 + 8]);
        qf[ks][2] = __float_as_uint(Ps[(8*ks+t+4)*PPAD + m0    ]);
        qf[ks][3] = __float_as_uint(Ps[(8*ks+t+4)*PPAD + m0 + 8]);
    }

    float m2[2] = {-1e30f, -1e30f};
    float l[2]  = {0.0f, 0.0f};
    float ao[8][4] = {};
    const float cs = 0.125f * 1.4426950408889634f;

    const int NT = S_ / 128;
    for (int it = 0; it < NT; it++) {
        int buf = it & 1;
        asm volatile("cp.async.wait_group 0;");
        __syncthreads();

        if (it + 1 < NT) {
            int kv0 = (it + 1) * 128;
            uint32_t kd = ks_b + (buf ^ 1) * 128 * KPAD * 4;
            uint32_t vd = vs_b + (buf ^ 1) * 128 * VPAD * 4;
            #pragma unroll
            for (int j = 0; j < 8; j++) {
                int id = tid + 256 * j;
                int r = id >> 4, c = id & 15;
                cpa16(kd + (r * KPAD + c * 4) * 4, kb + (size_t)(kv0 + r) * D_ + c * 4);
                cpa16(vd + (r * VPAD + c * 4) * 4, vb + (size_t)(kv0 + r) * D_ + c * 4);
            }
            asm volatile("cp.async.commit_group;");
        }

        const float* Kt = Ks + buf * 128 * KPAD;
        const float* Vt = Vs + buf * 128 * VPAD;

        float s[16][4] = {};
        #pragma unroll
        for (int ni = 0; ni < 16; ni++) {
            #pragma unroll
            for (int ks = 0; ks < 8; ks++) {
                uint32_t bf[2];
                bf[0] = __float_as_uint(Kt[(8*ni+g)*KPAD + 8*ks + t    ]);
                bf[1] = __float_as_uint(Kt[(8*ni+g)*KPAD + 8*ks + t + 4]);
                mma_tf32(s[ni], qf[ks], bf);
            }
        }

        float mx0 = -1e30f, mx1 = -1e30f;
        #pragma unroll
        for (int ni = 0; ni < 16; ni++) {
            mx0 = fmaxf(mx0, fmaxf(s[ni][0], s[ni][1]));
            mx1 = fmaxf(mx1, fmaxf(s[ni][2], s[ni][3]));
        }
        mx0 = fmaxf(mx0, __shfl_xor_sync(~0u, mx0, 1));
        mx0 = fmaxf(mx0, __shfl_xor_sync(~0u, mx0, 2));
        mx1 = fmaxf(mx1, __shfl_xor_sync(~0u, mx1, 1));
        mx1 = fmaxf(mx1, __shfl_xor_sync(~0u, mx1, 2));
        float nm0 = fmaxf(m2[0], mx0 * cs);
        float nm1 = fmaxf(m2[1], mx1 * cs);
        float cr0 = ex2f(m2[0] - nm0);
        float cr1 = ex2f(m2[1] - nm1);
        m2[0] = nm0; m2[1] = nm1;

        float sum0 = 0.0f, sum1 = 0.0f;
        #pragma unroll
        for (int ni = 0; ni < 16; ni++) {
            s[ni][0] = ex2f(fmaf(s[ni][0], cs, -nm0));
            s[ni][1] = ex2f(fmaf(s[ni][1], cs, -nm0));
            s[ni][2] = ex2f(fmaf(s[ni][2], cs, -nm1));
            s[ni][3] = ex2f(fmaf(s[ni][3], cs, -nm1));
            sum0 += s[ni][0] + s[ni][1];
            sum1 += s[ni][2] + s[ni][3];
        }
        sum0 += __shfl_xor_sync(~0u, sum0, 1);
        sum0 += __shfl_xor_sync(~0u, sum0, 2);
        sum1 += __shfl_xor_sync(~0u, sum1, 1);
        sum1 += __shfl_xor_sync(~0u, sum1, 2);
        l[0] = l[0] * cr0 + sum0;
        l[1] = l[1] * cr1 + sum1;

        #pragma unroll
        for (int ni = 0; ni < 8; ni++) {
            ao[ni][0] *= cr0; ao[ni][1] *= cr0;
            ao[ni][2] *= cr1; ao[ni][3] *= cr1;
        }

        #pragma unroll
        for (int ni = 0; ni < 16; ni++) {
            int col = 8 * ni + 2 * t;
            Ps[(col    )*PPAD + m0    ] = s[ni][0];
            Ps[(col + 1)*PPAD + m0    ] = s[ni][1];
            Ps[(col    )*PPAD + m0 + 8] = s[ni][2];
            Ps[(col + 1)*PPAD + m0 + 8] = s[ni][3];
        }
        __syncwarp();

        #pragma unroll
        for (int kst = 0; kst < 16; kst++) {
            uint32_t af[4];
            af[0] = __float_as_uint(Ps[(8*kst+t  )*PPAD + m0    ]);
            af[1] = __float_as_uint(Ps[(8*kst+t  )*PPAD + m0 + 8]);
            af[2] = __float_as_uint(Ps[(8*kst+t+4)*PPAD + m0    ]);
            af[3] = __float_as_uint(Ps[(8*kst+t+4)*PPAD + m0 + 8]);
            #pragma unroll
            for (int ni = 0; ni < 8; ni++) {
                uint32_t bf[2];
                bf[0] = __float_as_uint(Vt[(8*kst+t  )*VPAD + 8*ni + g]);
                bf[1] = __float_as_uint(Vt[(8*kst+t+4)*VPAD + 8*ni + g]);
                mma_tf32(ao[ni], af, bf);
            }
        }
    }

    float inv0 = 1.0f / l[0], inv1 = 1.0f / l[1];
    size_t base0 = ((size_t)b * S_ + q0 + m0) * D_ + h * DH_;
    size_t base1 = base0 + 8 * (size_t)D_;
    #pragma unroll
    for (int ni = 0; ni < 8; ni++) {
        int col = 8 * ni + 2 * t;
        float2 o0 = make_float2(ao[ni][0] * inv0, ao[ni][1] * inv0);
        float2 o1 = make_float2(ao[ni][2] * inv1, ao[ni][3] * inv1);
        *(float2*)(ctx + base0 + col) = o0;
        *(float2*)(ctx + base1 + col) = o1;
    }
}

// ---------------- launch ----------------
extern "C" void kernel_launch(void* const* d_in, const int* in_sizes, int n_in,
                              void* d_out, int out_size)
{
    const float* x    = (const float*)d_in[0];
    const float* ln1s = (const float*)d_in[1];
    const float* ln1b = (const float*)d_in[2];
    const float* wk   = (const float*)d_in[3];
    const float* wq   = (const float*)d_in[4];
    const float* wv   = (const float*)d_in[5];
    const float* wo   = (const float*)d_in[6];
    const float* ln2s = (const float*)d_in[7];
    const float* ln2b = (const float*)d_in[8];
    const float* w1   = (const float*)d_in[9];
    const float* b1   = (const float*)d_in[10];
    const float* w2   = (const float*)d_in[11];
    const float* b2   = (const float*)d_in[12];
    float* out = (float*)d_out;

    float *h, *q, *kb, *v, *ctx, *mlpin, *h2, *ff1;
    cudaGetSymbolAddress((void**)&h,     g_h);
    cudaGetSymbolAddress((void**)&q,     g_q);
    cudaGetSymbolAddress((void**)&kb,    g_k);
    cudaGetSymbolAddress((void**)&v,     g_v);
    cudaGetSymbolAddress((void**)&ctx,   g_ctx);
    cudaGetSymbolAddress((void**)&mlpin, g_mlpin);
    cudaGetSymbolAddress((void**)&h2,    g_h2);
    cudaGetSymbolAddress((void**)&ff1,   g_ff1);

    cudaFuncSetAttribute(flash_k, cudaFuncAttributeMaxDynamicSharedMemorySize, FLASH_SMEM);
    cudaFuncSetAttribute(gemm_tc<0>, cudaFuncAttributeMaxDynamicSharedMemorySize, GEMM_SMEM);
    cudaFuncSetAttribute(gemm_tc<1>, cudaFuncAttributeMaxDynamicSharedMemorySize, GEMM_SMEM);
    cudaFuncSetAttribute(gemm_tc<2>, cudaFuncAttributeMaxDynamicSharedMemorySize, GEMM_SMEM);
    cudaFuncSetAttribute(gemm_tc<3>, cudaFuncAttributeMaxDynamicSharedMemorySize, GEMM_SMEM);

    layernorm_k<<<R_, 256>>>(x, ln1s, ln1b, h);
    gemm_tc<0><<<dim3(D_/128, R_/128), 256, GEMM_SMEM>>>(h, wq, q,  R_, D_, D_, nullptr, nullptr);
    gemm_tc<0><<<dim3(D_/128, R_/128), 256, GEMM_SMEM>>>(h, wk, kb, R_, D_, D_, nullptr, nullptr);
    gemm_tc<0><<<dim3(D_/128, R_/128), 256, GEMM_SMEM>>>(h, wv, v,  R_, D_, D_, nullptr, nullptr);
    {
        int total = B_ * S_ * H_ * (DH_/2);
        rope_k<<<(total + 255) / 256, 256>>>(q, kb);
    }
    flash_k<<<dim3(S_/128, B_*H_), 256, FLASH_SMEM>>>(q, kb, v, ctx);
    gemm_tc<1><<<dim3(D_/128, R_/128), 256, GEMM_SMEM>>>(ctx, wo, mlpin, R_, D_, D_, nullptr, x);
    layernorm_k<<<R_, 256>>>(mlpin, ln2s, ln2b, h2);
    gemm_tc<2><<<dim3(M_/128, R_/128), 256, GEMM_SMEM>>>(h2,  w1, ff1, R_, M_, D_, b1, nullptr);
    gemm_tc<3><<<dim3(D_/128, R_/128), 256, GEMM_SMEM>>>(ff1, w2, out, R_, D_, M_, b2, mlpin);
}